// round 13
// baseline (speedup 1.0000x reference)
#include <cuda_runtime.h>
#include <cuda_bf16.h>
#include <cstdint>
#include <math.h>

#define B_    32
#define D_    768
#define NH_   12
#define HD_   64
#define L_    12
#define MLP_D 3072
#define S0_   197
#define SMAX_ 237
#define NE_   10
#define LP_   40
#define NPL_  5
#define NC_   100
#define MALL  (B_*SMAX_)   // 7584 rows

// ================= helpers =================
__device__ __forceinline__ uint32_t smem_to_u32(const void* p) {
    uint32_t a;
    asm("{ .reg .u64 t; cvta.to.shared.u64 t, %1; cvt.u32.u64 %0, t; }" : "=r"(a) : "l"(p));
    return a;
}
#define STS128(r0, r1, r2, r3, sa) \
    asm volatile("st.shared.v4.b32 [%0], {%1, %2, %3, %4};" \
                 :: "r"(sa), "r"(r0), "r"(r1), "r"(r2), "r"(r3) : "memory")
#define SMEM_SWIZZLE_128B(bo) ((bo) ^ (((bo) >> 3) & 0x70))

__device__ __forceinline__ void ldsm4(uint32_t addr, uint32_t r[4]) {
    asm volatile("ldmatrix.sync.aligned.m8n8.x4.shared.b16 {%0,%1,%2,%3}, [%4];"
                 : "=r"(r[0]), "=r"(r[1]), "=r"(r[2]), "=r"(r[3]) : "r"(addr));
}
__device__ __forceinline__ void ldsm2(uint32_t addr, uint32_t r[2]) {
    asm volatile("ldmatrix.sync.aligned.m8n8.x2.shared.b16 {%0,%1}, [%2];"
                 : "=r"(r[0]), "=r"(r[1]) : "r"(addr));
}
__device__ __forceinline__ void mma16816(float c[4], const uint32_t a[4], const uint32_t b[2]) {
    asm volatile("mma.sync.aligned.m16n8k16.row.col.f32.bf16.bf16.f32 "
                 "{%0,%1,%2,%3}, {%4,%5,%6,%7}, {%8,%9}, {%0,%1,%2,%3};"
                 : "+f"(c[0]), "+f"(c[1]), "+f"(c[2]), "+f"(c[3])
                 : "r"(a[0]), "r"(a[1]), "r"(a[2]), "r"(a[3]), "r"(b[0]), "r"(b[1]));
}

// ================= scratch (device globals) =================
__device__ float g_x  [MALL * D_];
__device__ float g_qkv[MALL * 3 * D_];
__device__ float g_bp [B_ * NPL_ * LP_ * D_];
__device__ __nv_bfloat16 g_hh[MALL * D_],    g_hl[MALL * D_];
__device__ __nv_bfloat16 g_oh[MALL * D_],    g_ol[MALL * D_];
__device__ __nv_bfloat16 g_mh[MALL * MLP_D], g_ml[MALL * MLP_D];
// transposed+split weights: [N][K] bf16 per layer
__device__ __nv_bfloat16 g_wq_h[L_ * 3 * D_ * D_],   g_wq_l[L_ * 3 * D_ * D_];
__device__ __nv_bfloat16 g_wp_h[L_ * D_ * D_],       g_wp_l[L_ * D_ * D_];
__device__ __nv_bfloat16 g_w1_h[L_ * MLP_D * D_],    g_w1_l[L_ * MLP_D * D_];
__device__ __nv_bfloat16 g_w2_h[L_ * D_ * MLP_D],    g_w2_l[L_ * D_ * MLP_D];

// ================= weight transpose + bf16 split =================
__global__ void wsplit_kernel(const float* __restrict__ W, __nv_bfloat16* __restrict__ Wh,
                              __nv_bfloat16* __restrict__ Wl, int K, int N)
{
    __shared__ float tile[32][33];
    const size_t zo = (size_t)blockIdx.z * K * N;
    const float* Wz = W + zo;
    __nv_bfloat16* Whz = Wh + zo;
    __nv_bfloat16* Wlz = Wl + zo;
    int n0 = blockIdx.x * 32, k0 = blockIdx.y * 32;
    int tx = threadIdx.x, ty = threadIdx.y;
#pragma unroll
    for (int i = 0; i < 4; i++)
        tile[ty + 8 * i][tx] = Wz[(size_t)(k0 + ty + 8 * i) * N + n0 + tx];
    __syncthreads();
#pragma unroll
    for (int i = 0; i < 4; i++) {
        int n = n0 + ty + 8 * i, k = k0 + tx;
        float v = tile[tx][ty + 8 * i];
        __nv_bfloat16 hi = __float2bfloat16(v);
        Whz[(size_t)n * K + k] = hi;
        Wlz[(size_t)n * K + k] = __float2bfloat16(v - __bfloat162float(hi));
    }
}

// ================= smem tile loader: 128 rows x 64 bf16, SW128 =================
__device__ __forceinline__ void load_tile_bf16(const __nv_bfloat16* __restrict__ src,
                                               uint32_t smem_dst, int row0, int Rvalid,
                                               int K, int kc, int tid)
{
    // 128 rows * 8 uint4 = 1024 uint4; 256 threads -> 4 each
#pragma unroll
    for (int q = 0; q < 4; q++) {
        int idx = tid + q * 256;
        int r = idx >> 3, c = idx & 7;
        uint4 v = make_uint4(0u, 0u, 0u, 0u);
        int gr = row0 + r;
        if (gr < Rvalid)
            v = *reinterpret_cast<const uint4*>(src + (size_t)gr * K + kc + c * 8);
        uint32_t off = (uint32_t)(r * 128 + c * 16);
        STS128(v.x, v.y, v.z, v.w, smem_dst + SMEM_SWIZZLE_128B(off));
    }
}

// ================= split-bf16 warp-MMA GEMM =================
// C[m,n] = epi( sum_k A[m,k]*B[n,k] + bias[n] [+ Xres] )
// A,B as hi/lo bf16 (3 product passes). CTA tile 128x128, BK=64, 8 warps of 64x32.
template<int ACT, bool RESID, bool OSPLIT>
__global__ void __launch_bounds__(256) mma_gemm(
    const __nv_bfloat16* __restrict__ Ah, const __nv_bfloat16* __restrict__ Al,
    const __nv_bfloat16* __restrict__ Bh, const __nv_bfloat16* __restrict__ Bl,
    const float* __restrict__ bias, const float* __restrict__ Xres,
    float* __restrict__ Cf, __nv_bfloat16* __restrict__ Ch, __nv_bfloat16* __restrict__ Cl,
    int M, int N, int K)
{
    __shared__ __align__(1024) __nv_bfloat16 smA[128 * 64];
    __shared__ __align__(1024) __nv_bfloat16 smB[128 * 64];

    const int tid  = threadIdx.x;
    const int wid  = tid >> 5;
    const int lane = tid & 31;
    const int m0 = blockIdx.y * 128, n0 = blockIdx.x * 128;
    const int m0w = (wid & 1) * 64;        // warp row offset in CTA tile
    const int n0w = (wid >> 1) * 32;       // warp col offset

    const uint32_t sA = smem_to_u32(smA);
    const uint32_t sB = smem_to_u32(smB);

    float acc[4][4][4];
#pragma unroll
    for (int i = 0; i < 4; i++)
#pragma unroll
        for (int j = 0; j < 4; j++)
#pragma unroll
            for (int q = 0; q < 4; q++) acc[i][j][q] = 0.f;

    // precompute ldmatrix lane address components
    const int aRow = m0w + (lane & 15);          // + mt*16
    const int aColB = (lane >> 4) << 4;          // 0 or 16 bytes
    const int bRow = n0w + (lane & 7);           // + nt*8
    const int bColB = ((lane >> 3) & 1) << 4;

    const int nch = K >> 6;
#pragma unroll 1
    for (int p = 0; p < 3; p++) {
        const __nv_bfloat16* Asrc = (p == 1) ? Al : Ah;
        const __nv_bfloat16* Bsrc = (p == 2) ? Bl : Bh;
#pragma unroll 1
        for (int c = 0; c < nch; c++) {
            __syncthreads();
            load_tile_bf16(Asrc, sA, m0, M, K, c << 6, tid);
            load_tile_bf16(Bsrc, sB, n0, N, K, c << 6, tid);
            __syncthreads();
#pragma unroll
            for (int ks = 0; ks < 4; ks++) {
                uint32_t af[4][4], bf[4][2];
#pragma unroll
                for (int mt = 0; mt < 4; mt++) {
                    uint32_t off = (uint32_t)((aRow + mt * 16) * 128 + ks * 32 + aColB);
                    ldsm4(sA + SMEM_SWIZZLE_128B(off), af[mt]);
                }
#pragma unroll
                for (int nt = 0; nt < 4; nt++) {
                    uint32_t off = (uint32_t)((bRow + nt * 8) * 128 + ks * 32 + bColB);
                    ldsm2(sB + SMEM_SWIZZLE_128B(off), bf[nt]);
                }
#pragma unroll
                for (int mt = 0; mt < 4; mt++)
#pragma unroll
                    for (int nt = 0; nt < 4; nt++)
                        mma16816(acc[mt][nt], af[mt], bf[nt]);
            }
        }
    }

    // ---- epilogue ----
    const int rr = lane >> 2, cc = (lane & 3) * 2;
#pragma unroll
    for (int mt = 0; mt < 4; mt++) {
#pragma unroll
        for (int half = 0; half < 2; half++) {
            int r = m0 + m0w + mt * 16 + rr + half * 8;
            if (r >= M) continue;
#pragma unroll
            for (int nt = 0; nt < 4; nt++) {
                int cg = n0 + n0w + nt * 8 + cc;
                float v0 = acc[mt][nt][half * 2 + 0] + bias[cg];
                float v1 = acc[mt][nt][half * 2 + 1] + bias[cg + 1];
                if (RESID) {
                    float2 xr = *reinterpret_cast<const float2*>(Xres + (size_t)r * N + cg);
                    v0 += xr.x; v1 += xr.y;
                }
                if (ACT == 1) {
                    v0 = 0.5f * v0 * (1.0f + erff(v0 * 0.70710678118654752f));
                    v1 = 0.5f * v1 * (1.0f + erff(v1 * 0.70710678118654752f));
                }
                size_t idx = (size_t)r * N + cg;
                if (OSPLIT) {
                    __nv_bfloat16 h0 = __float2bfloat16(v0);
                    __nv_bfloat16 h1 = __float2bfloat16(v1);
                    *reinterpret_cast<__nv_bfloat162*>(Ch + idx) = __halves2bfloat162(h0, h1);
                    *reinterpret_cast<__nv_bfloat162*>(Cl + idx) =
                        __floats2bfloat162_rn(v0 - __bfloat162float(h0), v1 - __bfloat162float(h1));
                } else {
                    float2 o; o.x = v0; o.y = v1;
                    *reinterpret_cast<float2*>(Cf + idx) = o;
                }
            }
        }
    }
}

// ================= patch embed (fp32 FFMA GEMM, small) =================
__global__ void patch_embed_kernel(const float* __restrict__ inp, const float* __restrict__ pw,
                                   const float* __restrict__ pb, const float* __restrict__ pos,
                                   float* __restrict__ x)
{
    __shared__ float As[16][68];
    __shared__ float Ws[16][68];
    const int tid = threadIdx.x;
    const int m0 = blockIdx.y * 64, n0 = blockIdx.x * 64;
    const int tx = tid & 15, ty = tid >> 4;
    const int la_m = tid >> 2, la_k = (tid & 3) * 4;
    const int lw_n = tid >> 2, lw_k = (tid & 3) * 4;
    const int gm = m0 + la_m;
    const int ab = gm / 196, ap = gm % 196;
    const int apy = ap / 14, apx = ap % 14;

    float acc[4][4];
#pragma unroll
    for (int i = 0; i < 4; i++)
#pragma unroll
        for (int j = 0; j < 4; j++) acc[i][j] = 0.f;

    for (int k0 = 0; k0 < 768; k0 += 16) {
        int k = k0 + la_k;
        int c = k >> 8, ii = (k >> 4) & 15, jj = k & 15;
        const float* src = inp + (((size_t)ab * 3 + c) * 224 + (apy * 16 + ii)) * 224 + apx * 16 + jj;
        float4 av = *(const float4*)src;
        As[la_k + 0][la_m] = av.x;
        As[la_k + 1][la_m] = av.y;
        As[la_k + 2][la_m] = av.z;
        As[la_k + 3][la_m] = av.w;
        float4 wv = *(const float4*)(pw + (size_t)(n0 + lw_n) * 768 + k0 + lw_k);
        Ws[lw_k + 0][lw_n] = wv.x;
        Ws[lw_k + 1][lw_n] = wv.y;
        Ws[lw_k + 2][lw_n] = wv.z;
        Ws[lw_k + 3][lw_n] = wv.w;
        __syncthreads();
#pragma unroll
        for (int kk = 0; kk < 16; kk++) {
            float4 a4 = *(const float4*)&As[kk][ty * 4];
            float4 b4 = *(const float4*)&Ws[kk][tx * 4];
            float a[4] = {a4.x, a4.y, a4.z, a4.w};
            float b[4] = {b4.x, b4.y, b4.z, b4.w};
#pragma unroll
            for (int i = 0; i < 4; i++)
#pragma unroll
                for (int j = 0; j < 4; j++) acc[i][j] += a[i] * b[j];
        }
        __syncthreads();
    }
#pragma unroll
    for (int i = 0; i < 4; i++) {
        int m = m0 + ty * 4 + i;
        int bb = m / 196, pp = m % 196;
#pragma unroll
        for (int j = 0; j < 4; j++) {
            int n = n0 + tx * 4 + j;
            float v = acc[i][j] + pb[n] + pos[(size_t)(1 + pp) * 768 + n];
            x[((size_t)bb * SMAX_ + 1 + pp) * 768 + n] = v;
        }
    }
}

__global__ void cls_pos_kernel(const float* __restrict__ cls, const float* __restrict__ pos,
                               float* __restrict__ x)
{
    int i = blockIdx.x * 256 + threadIdx.x;
    int b = i / 768, d = i % 768;
    x[(size_t)b * SMAX_ * 768 + d] = cls[d] + pos[d];
}

__global__ void build_bp_kernel(const float* __restrict__ prompts, const int* __restrict__ eid,
                                const float* __restrict__ pos, float* __restrict__ bp)
{
    int i = blockIdx.x * 256 + threadIdx.x;
    int d = i % 768;
    int r = i / 768;
    int t = r % LP_; r /= LP_;
    int pl = r % NPL_;
    int b = r / NPL_;
    int e = eid[b];
    bp[i] = prompts[(((size_t)pl * NE_ + e) * LP_ + t) * 768 + d] + pos[d];
}

__global__ void append_kernel(const float* __restrict__ bp, float* __restrict__ x, int pl)
{
    int i = blockIdx.x * 256 + threadIdx.x;
    int d = i % 768;
    int r = i / 768;
    int t = r % LP_;
    int b = r / LP_;
    x[((size_t)b * SMAX_ + S0_ + t) * 768 + d] =
        bp[(((size_t)b * NPL_ + pl) * LP_ + t) * 768 + d];
}

// ---- LayerNorm -> bf16 hi/lo splits ----
__global__ void ln_kernel(const float* __restrict__ x, const float* __restrict__ s,
                          const float* __restrict__ bb, __nv_bfloat16* __restrict__ hh,
                          __nv_bfloat16* __restrict__ hl)
{
    int row = blockIdx.x;
    int t = threadIdx.x;
    const float* xr = x + (size_t)row * 768;
    float v0 = xr[t], v1 = xr[t + 256], v2 = xr[t + 512];
    __shared__ float red[256];
    red[t] = v0 + v1 + v2;
    __syncthreads();
    for (int o = 128; o > 0; o >>= 1) { if (t < o) red[t] += red[t + o]; __syncthreads(); }
    float mean = red[0] * (1.f / 768.f);
    __syncthreads();
    float d0 = v0 - mean, d1 = v1 - mean, d2 = v2 - mean;
    red[t] = d0 * d0 + d1 * d1 + d2 * d2;
    __syncthreads();
    for (int o = 128; o > 0; o >>= 1) { if (t < o) red[t] += red[t + o]; __syncthreads(); }
    float rstd = rsqrtf(red[0] * (1.f / 768.f) + 1e-6f);
    float h0 = d0 * rstd * s[t] + bb[t];
    float h1 = d1 * rstd * s[t + 256] + bb[t + 256];
    float h2 = d2 * rstd * s[t + 512] + bb[t + 512];
    size_t ro = (size_t)row * 768;
    __nv_bfloat16 a0 = __float2bfloat16(h0), a1 = __float2bfloat16(h1), a2 = __float2bfloat16(h2);
    hh[ro + t] = a0;          hl[ro + t]       = __float2bfloat16(h0 - __bfloat162float(a0));
    hh[ro + t + 256] = a1;    hl[ro + t + 256] = __float2bfloat16(h1 - __bfloat162float(a1));
    hh[ro + t + 512] = a2;    hl[ro + t + 512] = __float2bfloat16(h2 - __bfloat162float(a2));
}

// ---- fused attention: one block per (q, head, batch); writes bf16 split o ----
__global__ void attn_kernel(const float* __restrict__ qkv, __nv_bfloat16* __restrict__ oh,
                            __nv_bfloat16* __restrict__ ol, int S)
{
    int qi = blockIdx.x, hh = blockIdx.y, b = blockIdx.z;
    int t = threadIdx.x;
    __shared__ float qs[HD_];
    __shared__ float sc[SMAX_];
    __shared__ float red[256];
    const float* base = qkv + (size_t)b * SMAX_ * 2304;

    if (t < HD_) qs[t] = base[(size_t)qi * 2304 + hh * HD_ + t];
    __syncthreads();

    if (t < S) {
        const float* kr = base + (size_t)t * 2304 + 768 + hh * HD_;
        float acc = 0.f;
#pragma unroll
        for (int d = 0; d < HD_; d++) acc += qs[d] * kr[d];
        sc[t] = acc * 0.125f;
    }
    __syncthreads();

    red[t] = (t < S) ? sc[t] : -1e30f;
    __syncthreads();
    for (int o2 = 128; o2 > 0; o2 >>= 1) { if (t < o2) red[t] = fmaxf(red[t], red[t + o2]); __syncthreads(); }
    float mx = red[0];
    __syncthreads();
    float e = (t < S) ? __expf(sc[t] - mx) : 0.f;
    red[t] = e;
    __syncthreads();
    for (int o2 = 128; o2 > 0; o2 >>= 1) { if (t < o2) red[t] += red[t + o2]; __syncthreads(); }
    float inv = 1.f / red[0];
    __syncthreads();
    if (t < S) sc[t] = e * inv;
    __syncthreads();

    if (t < HD_) {
        const float* vr = base + 1536 + hh * HD_ + t;
        float acc = 0.f;
        for (int k2 = 0; k2 < S; k2++) acc += sc[k2] * vr[(size_t)k2 * 2304];
        size_t idx = ((size_t)b * SMAX_ + qi) * 768 + hh * HD_ + t;
        __nv_bfloat16 hi = __float2bfloat16(acc);
        oh[idx] = hi;
        ol[idx] = __float2bfloat16(acc - __bfloat162float(hi));
    }
}

// ---- final LN(token 0) + expert head ----
__global__ void head_kernel(const float* __restrict__ x, const float* __restrict__ ns,
                            const float* __restrict__ nb, const int* __restrict__ eid,
                            const float* __restrict__ hw, const float* __restrict__ hb,
                            float* __restrict__ out)
{
    int b = blockIdx.x, t = threadIdx.x;
    __shared__ float feat[768];
    __shared__ float red[256];
    const float* xr = x + (size_t)b * SMAX_ * 768;
    float v0 = xr[t], v1 = xr[t + 256], v2 = xr[t + 512];
    red[t] = v0 + v1 + v2;
    __syncthreads();
    for (int o = 128; o > 0; o >>= 1) { if (t < o) red[t] += red[t + o]; __syncthreads(); }
    float mean = red[0] * (1.f / 768.f);
    __syncthreads();
    float d0 = v0 - mean, d1 = v1 - mean, d2 = v2 - mean;
    red[t] = d0 * d0 + d1 * d1 + d2 * d2;
    __syncthreads();
    for (int o = 128; o > 0; o >>= 1) { if (t < o) red[t] += red[t + o]; __syncthreads(); }
    float rstd = rsqrtf(red[0] * (1.f / 768.f) + 1e-6f);
    feat[t]       = d0 * rstd * ns[t]       + nb[t];
    feat[t + 256] = d1 * rstd * ns[t + 256] + nb[t + 256];
    feat[t + 512] = d2 * rstd * ns[t + 512] + nb[t + 512];
    __syncthreads();

    int e = eid[b];
    if (t < NC_) {
        float acc = hb[(size_t)e * NC_ + t];
        const float* w = hw + (size_t)e * 768 * NC_ + t;
        for (int d = 0; d < 768; d++) acc += feat[d] * w[(size_t)d * NC_];
        out[(size_t)b * NC_ + t] = acc;
    }
}

// ============================================================
extern "C" void kernel_launch(void* const* d_in, const int* in_sizes, int n_in,
                              void* d_out, int out_size)
{
    const float* inputs  = (const float*)d_in[0];
    const int*   eids    = (const int*)  d_in[1];
    const float* patch_w = (const float*)d_in[2];
    const float* patch_b = (const float*)d_in[3];
    const float* cls     = (const float*)d_in[4];
    const float* pos     = (const float*)d_in[5];
    const float* ln1_s   = (const float*)d_in[6];
    const float* ln1_b   = (const float*)d_in[7];
    const float* qkv_w   = (const float*)d_in[8];
    const float* qkv_b   = (const float*)d_in[9];
    const float* proj_w  = (const float*)d_in[10];
    const float* proj_b  = (const float*)d_in[11];
    const float* ln2_s   = (const float*)d_in[12];
    const float* ln2_b   = (const float*)d_in[13];
    const float* fc1_w   = (const float*)d_in[14];
    const float* fc1_b   = (const float*)d_in[15];
    const float* fc2_w   = (const float*)d_in[16];
    const float* fc2_b   = (const float*)d_in[17];
    const float* norm_s  = (const float*)d_in[18];
    const float* norm_b  = (const float*)d_in[19];
    const float* prompts = (const float*)d_in[20];
    const float* head_w  = (const float*)d_in[21];
    const float* head_b  = (const float*)d_in[22];
    float* out = (float*)d_out;

    float *x, *qkv, *bp;
    __nv_bfloat16 *hh, *hl, *oh, *ol, *mh, *ml;
    __nv_bfloat16 *wqh, *wql, *wph, *wpl, *w1h, *w1l, *w2h, *w2l;
    cudaGetSymbolAddress((void**)&x,   g_x);
    cudaGetSymbolAddress((void**)&qkv, g_qkv);
    cudaGetSymbolAddress((void**)&bp,  g_bp);
    cudaGetSymbolAddress((void**)&hh,  g_hh);
    cudaGetSymbolAddress((void**)&hl,  g_hl);
    cudaGetSymbolAddress((void**)&oh,  g_oh);
    cudaGetSymbolAddress((void**)&ol,  g_ol);
    cudaGetSymbolAddress((void**)&mh,  g_mh);
    cudaGetSymbolAddress((void**)&ml,  g_ml);
    cudaGetSymbolAddress((void**)&wqh, g_wq_h);
    cudaGetSymbolAddress((void**)&wql, g_wq_l);
    cudaGetSymbolAddress((void**)&wph, g_wp_h);
    cudaGetSymbolAddress((void**)&wpl, g_wp_l);
    cudaGetSymbolAddress((void**)&w1h, g_w1_h);
    cudaGetSymbolAddress((void**)&w1l, g_w1_l);
    cudaGetSymbolAddress((void**)&w2h, g_w2_h);
    cudaGetSymbolAddress((void**)&w2l, g_w2_l);

    // ---- weight transpose + split (once per launch) ----
    wsplit_kernel<<<dim3(3 * D_ / 32, D_ / 32, L_), dim3(32, 8)>>>(qkv_w, wqh, wql, D_, 3 * D_);
    wsplit_kernel<<<dim3(D_ / 32, D_ / 32, L_),     dim3(32, 8)>>>(proj_w, wph, wpl, D_, D_);
    wsplit_kernel<<<dim3(MLP_D / 32, D_ / 32, L_),  dim3(32, 8)>>>(fc1_w, w1h, w1l, D_, MLP_D);
    wsplit_kernel<<<dim3(D_ / 32, MLP_D / 32, L_),  dim3(32, 8)>>>(fc2_w, w2h, w2l, MLP_D, D_);

    // ---- patch embed + cls + prompts ----
    patch_embed_kernel<<<dim3(12, 98), 256>>>(inputs, patch_w, patch_b, pos, x);
    cls_pos_kernel<<<(B_ * 768) / 256, 256>>>(cls, pos, x);
    build_bp_kernel<<<(B_ * NPL_ * LP_ * 768) / 256, 256>>>(prompts, eids, pos, bp);

    const int MT = (MALL + 127) / 128;  // 60
    for (int i = 0; i < L_; i++) {
        int S = (i < NPL_) ? SMAX_ : S0_;
        if (i < NPL_)
            append_kernel<<<(B_ * LP_ * 768) / 256, 256>>>(bp, x, i);

        ln_kernel<<<MALL, 256>>>(x, ln1_s + (size_t)i * D_, ln1_b + (size_t)i * D_, hh, hl);
        mma_gemm<0, false, false><<<dim3(18, MT), 256>>>(
            hh, hl, wqh + (size_t)i * 3 * D_ * D_, wql + (size_t)i * 3 * D_ * D_,
            qkv_b + (size_t)i * 3 * D_, nullptr, qkv, nullptr, nullptr, MALL, 3 * D_, D_);
        attn_kernel<<<dim3(S, NH_, B_), 256>>>(qkv, oh, ol, S);
        mma_gemm<0, true, false><<<dim3(6, MT), 256>>>(
            oh, ol, wph + (size_t)i * D_ * D_, wpl + (size_t)i * D_ * D_,
            proj_b + (size_t)i * D_, x, x, nullptr, nullptr, MALL, D_, D_);
        ln_kernel<<<MALL, 256>>>(x, ln2_s + (size_t)i * D_, ln2_b + (size_t)i * D_, hh, hl);
        mma_gemm<1, false, true><<<dim3(24, MT), 256>>>(
            hh, hl, w1h + (size_t)i * MLP_D * D_, w1l + (size_t)i * MLP_D * D_,
            fc1_b + (size_t)i * MLP_D, nullptr, nullptr, mh, ml, MALL, MLP_D, D_);
        mma_gemm<0, true, false><<<dim3(6, MT), 256>>>(
            mh, ml, w2h + (size_t)i * D_ * MLP_D, w2l + (size_t)i * D_ * MLP_D,
            fc2_b + (size_t)i * D_, x, x, nullptr, nullptr, MALL, D_, MLP_D);
    }

    head_kernel<<<B_, 256>>>(x, norm_s, norm_b, eids, head_w, head_b, out);
}

// round 14
// speedup vs baseline: 1.0019x; 1.0019x over previous
#include <cuda_runtime.h>
#include <cuda_bf16.h>
#include <cstdint>
#include <math.h>

#define B_    32
#define D_    768
#define NH_   12
#define HD_   64
#define L_    12
#define MLP_D 3072
#define S0_   197
#define SMAX_ 237
#define NE_   10
#define LP_   40
#define NPL_  5
#define NC_   100
#define MALL  (B_*SMAX_)   // 7584 rows

// ================= helpers =================
__device__ __forceinline__ uint32_t smem_to_u32(const void* p) {
    uint32_t a;
    asm("{ .reg .u64 t; cvta.to.shared.u64 t, %1; cvt.u32.u64 %0, t; }" : "=r"(a) : "l"(p));
    return a;
}
#define STS128(r0, r1, r2, r3, sa) \
    asm volatile("st.shared.v4.b32 [%0], {%1, %2, %3, %4};" \
                 :: "r"(sa), "r"(r0), "r"(r1), "r"(r2), "r"(r3) : "memory")
#define SMEM_SWIZZLE_128B(bo) ((bo) ^ (((bo) >> 3) & 0x70))

__device__ __forceinline__ void ldsm4(uint32_t addr, uint32_t r[4]) {
    asm volatile("ldmatrix.sync.aligned.m8n8.x4.shared.b16 {%0,%1,%2,%3}, [%4];"
                 : "=r"(r[0]), "=r"(r[1]), "=r"(r[2]), "=r"(r[3]) : "r"(addr));
}
__device__ __forceinline__ void ldsm2(uint32_t addr, uint32_t r[2]) {
    asm volatile("ldmatrix.sync.aligned.m8n8.x2.shared.b16 {%0,%1}, [%2];"
                 : "=r"(r[0]), "=r"(r[1]) : "r"(addr));
}
__device__ __forceinline__ void mma16816(float c[4], const uint32_t a[4], const uint32_t b[2]) {
    asm volatile("mma.sync.aligned.m16n8k16.row.col.f32.bf16.bf16.f32 "
                 "{%0,%1,%2,%3}, {%4,%5,%6,%7}, {%8,%9}, {%0,%1,%2,%3};"
                 : "+f"(c[0]), "+f"(c[1]), "+f"(c[2]), "+f"(c[3])
                 : "r"(a[0]), "r"(a[1]), "r"(a[2]), "r"(a[3]), "r"(b[0]), "r"(b[1]));
}

// ================= scratch (device globals) =================
__device__ float g_x  [MALL * D_];
__device__ float g_qkv[MALL * 3 * D_];
__device__ float g_bp [B_ * NPL_ * LP_ * D_];
__device__ __nv_bfloat16 g_hh[MALL * D_],    g_hl[MALL * D_];
__device__ __nv_bfloat16 g_oh[MALL * D_],    g_ol[MALL * D_];
__device__ __nv_bfloat16 g_mh[MALL * MLP_D], g_ml[MALL * MLP_D];
// transposed+split weights: [N][K] bf16 per layer
__device__ __nv_bfloat16 g_wq_h[L_ * 3 * D_ * D_],   g_wq_l[L_ * 3 * D_ * D_];
__device__ __nv_bfloat16 g_wp_h[L_ * D_ * D_],       g_wp_l[L_ * D_ * D_];
__device__ __nv_bfloat16 g_w1_h[L_ * MLP_D * D_],    g_w1_l[L_ * MLP_D * D_];
__device__ __nv_bfloat16 g_w2_h[L_ * D_ * MLP_D],    g_w2_l[L_ * D_ * MLP_D];

// ================= weight transpose + bf16 split =================
__global__ void wsplit_kernel(const float* __restrict__ W, __nv_bfloat16* __restrict__ Wh,
                              __nv_bfloat16* __restrict__ Wl, int K, int N)
{
    __shared__ float tile[32][33];
    const size_t zo = (size_t)blockIdx.z * K * N;
    const float* Wz = W + zo;
    __nv_bfloat16* Whz = Wh + zo;
    __nv_bfloat16* Wlz = Wl + zo;
    int n0 = blockIdx.x * 32, k0 = blockIdx.y * 32;
    int tx = threadIdx.x, ty = threadIdx.y;
#pragma unroll
    for (int i = 0; i < 4; i++)
        tile[ty + 8 * i][tx] = Wz[(size_t)(k0 + ty + 8 * i) * N + n0 + tx];
    __syncthreads();
#pragma unroll
    for (int i = 0; i < 4; i++) {
        int n = n0 + ty + 8 * i, k = k0 + tx;
        float v = tile[tx][ty + 8 * i];
        __nv_bfloat16 hi = __float2bfloat16(v);
        Whz[(size_t)n * K + k] = hi;
        Wlz[(size_t)n * K + k] = __float2bfloat16(v - __bfloat162float(hi));
    }
}

// ================= smem tile loader: 128 rows x 64 bf16, SW128 =================
__device__ __forceinline__ void load_tile_bf16(const __nv_bfloat16* __restrict__ src,
                                               uint32_t smem_dst, int row0, int Rvalid,
                                               int K, int kc, int tid)
{
    // 128 rows * 8 uint4 = 1024 uint4; 256 threads -> 4 each
#pragma unroll
    for (int q = 0; q < 4; q++) {
        int idx = tid + q * 256;
        int r = idx >> 3, c = idx & 7;
        uint4 v = make_uint4(0u, 0u, 0u, 0u);
        int gr = row0 + r;
        if (gr < Rvalid)
            v = *reinterpret_cast<const uint4*>(src + (size_t)gr * K + kc + c * 8);
        uint32_t off = (uint32_t)(r * 128 + c * 16);
        STS128(v.x, v.y, v.z, v.w, smem_dst + SMEM_SWIZZLE_128B(off));
    }
}

// ================= split-bf16 warp-MMA GEMM =================
// C[m,n] = epi( sum_k A[m,k]*B[n,k] + bias[n] [+ Xres] )
// A,B as hi/lo bf16 (3 product passes). CTA tile 128x128, BK=64, 8 warps of 64x32.
template<int ACT, bool RESID, bool OSPLIT>
__global__ void __launch_bounds__(256) mma_gemm(
    const __nv_bfloat16* __restrict__ Ah, const __nv_bfloat16* __restrict__ Al,
    const __nv_bfloat16* __restrict__ Bh, const __nv_bfloat16* __restrict__ Bl,
    const float* __restrict__ bias, const float* __restrict__ Xres,
    float* __restrict__ Cf, __nv_bfloat16* __restrict__ Ch, __nv_bfloat16* __restrict__ Cl,
    int M, int N, int K)
{
    __shared__ __align__(1024) __nv_bfloat16 smA[128 * 64];
    __shared__ __align__(1024) __nv_bfloat16 smB[128 * 64];

    const int tid  = threadIdx.x;
    const int wid  = tid >> 5;
    const int lane = tid & 31;
    const int m0 = blockIdx.y * 128, n0 = blockIdx.x * 128;
    const int m0w = (wid & 1) * 64;        // warp row offset in CTA tile
    const int n0w = (wid >> 1) * 32;       // warp col offset

    const uint32_t sA = smem_to_u32(smA);
    const uint32_t sB = smem_to_u32(smB);

    float acc[4][4][4];
#pragma unroll
    for (int i = 0; i < 4; i++)
#pragma unroll
        for (int j = 0; j < 4; j++)
#pragma unroll
            for (int q = 0; q < 4; q++) acc[i][j][q] = 0.f;

    // precompute ldmatrix lane address components
    const int aRow = m0w + (lane & 15);          // + mt*16
    const int aColB = (lane >> 4) << 4;          // 0 or 16 bytes
    const int bRow = n0w + (lane & 7);           // + nt*8
    const int bColB = ((lane >> 3) & 1) << 4;

    const int nch = K >> 6;
#pragma unroll 1
    for (int p = 0; p < 3; p++) {
        const __nv_bfloat16* Asrc = (p == 1) ? Al : Ah;
        const __nv_bfloat16* Bsrc = (p == 2) ? Bl : Bh;
#pragma unroll 1
        for (int c = 0; c < nch; c++) {
            __syncthreads();
            load_tile_bf16(Asrc, sA, m0, M, K, c << 6, tid);
            load_tile_bf16(Bsrc, sB, n0, N, K, c << 6, tid);
            __syncthreads();
#pragma unroll
            for (int ks = 0; ks < 4; ks++) {
                uint32_t af[4][4], bf[4][2];
#pragma unroll
                for (int mt = 0; mt < 4; mt++) {
                    uint32_t off = (uint32_t)((aRow + mt * 16) * 128 + ks * 32 + aColB);
                    ldsm4(sA + SMEM_SWIZZLE_128B(off), af[mt]);
                }
#pragma unroll
                for (int nt = 0; nt < 4; nt++) {
                    uint32_t off = (uint32_t)((bRow + nt * 8) * 128 + ks * 32 + bColB);
                    ldsm2(sB + SMEM_SWIZZLE_128B(off), bf[nt]);
                }
#pragma unroll
                for (int mt = 0; mt < 4; mt++)
#pragma unroll
                    for (int nt = 0; nt < 4; nt++)
                        mma16816(acc[mt][nt], af[mt], bf[nt]);
            }
        }
    }

    // ---- epilogue ----
    const int rr = lane >> 2, cc = (lane & 3) * 2;
#pragma unroll
    for (int mt = 0; mt < 4; mt++) {
#pragma unroll
        for (int half = 0; half < 2; half++) {
            int r = m0 + m0w + mt * 16 + rr + half * 8;
            if (r >= M) continue;
#pragma unroll
            for (int nt = 0; nt < 4; nt++) {
                int cg = n0 + n0w + nt * 8 + cc;
                float v0 = acc[mt][nt][half * 2 + 0] + bias[cg];
                float v1 = acc[mt][nt][half * 2 + 1] + bias[cg + 1];
                if (RESID) {
                    float2 xr = *reinterpret_cast<const float2*>(Xres + (size_t)r * N + cg);
                    v0 += xr.x; v1 += xr.y;
                }
                if (ACT == 1) {
                    v0 = 0.5f * v0 * (1.0f + erff(v0 * 0.70710678118654752f));
                    v1 = 0.5f * v1 * (1.0f + erff(v1 * 0.70710678118654752f));
                }
                size_t idx = (size_t)r * N + cg;
                if (OSPLIT) {
                    __nv_bfloat16 h0 = __float2bfloat16(v0);
                    __nv_bfloat16 h1 = __float2bfloat16(v1);
                    *reinterpret_cast<__nv_bfloat162*>(Ch + idx) = __halves2bfloat162(h0, h1);
                    *reinterpret_cast<__nv_bfloat162*>(Cl + idx) =
                        __floats2bfloat162_rn(v0 - __bfloat162float(h0), v1 - __bfloat162float(h1));
                } else {
                    float2 o; o.x = v0; o.y = v1;
                    *reinterpret_cast<float2*>(Cf + idx) = o;
                }
            }
        }
    }
}

// ================= patch embed (fp32 FFMA GEMM, small) =================
__global__ void patch_embed_kernel(const float* __restrict__ inp, const float* __restrict__ pw,
                                   const float* __restrict__ pb, const float* __restrict__ pos,
                                   float* __restrict__ x)
{
    __shared__ float As[16][68];
    __shared__ float Ws[16][68];
    const int tid = threadIdx.x;
    const int m0 = blockIdx.y * 64, n0 = blockIdx.x * 64;
    const int tx = tid & 15, ty = tid >> 4;
    const int la_m = tid >> 2, la_k = (tid & 3) * 4;
    const int lw_n = tid >> 2, lw_k = (tid & 3) * 4;
    const int gm = m0 + la_m;
    const int ab = gm / 196, ap = gm % 196;
    const int apy = ap / 14, apx = ap % 14;

    float acc[4][4];
#pragma unroll
    for (int i = 0; i < 4; i++)
#pragma unroll
        for (int j = 0; j < 4; j++) acc[i][j] = 0.f;

    for (int k0 = 0; k0 < 768; k0 += 16) {
        int k = k0 + la_k;
        int c = k >> 8, ii = (k >> 4) & 15, jj = k & 15;
        const float* src = inp + (((size_t)ab * 3 + c) * 224 + (apy * 16 + ii)) * 224 + apx * 16 + jj;
        float4 av = *(const float4*)src;
        As[la_k + 0][la_m] = av.x;
        As[la_k + 1][la_m] = av.y;
        As[la_k + 2][la_m] = av.z;
        As[la_k + 3][la_m] = av.w;
        float4 wv = *(const float4*)(pw + (size_t)(n0 + lw_n) * 768 + k0 + lw_k);
        Ws[lw_k + 0][lw_n] = wv.x;
        Ws[lw_k + 1][lw_n] = wv.y;
        Ws[lw_k + 2][lw_n] = wv.z;
        Ws[lw_k + 3][lw_n] = wv.w;
        __syncthreads();
#pragma unroll
        for (int kk = 0; kk < 16; kk++) {
            float4 a4 = *(const float4*)&As[kk][ty * 4];
            float4 b4 = *(const float4*)&Ws[kk][tx * 4];
            float a[4] = {a4.x, a4.y, a4.z, a4.w};
            float b[4] = {b4.x, b4.y, b4.z, b4.w};
#pragma unroll
            for (int i = 0; i < 4; i++)
#pragma unroll
                for (int j = 0; j < 4; j++) acc[i][j] += a[i] * b[j];
        }
        __syncthreads();
    }
#pragma unroll
    for (int i = 0; i < 4; i++) {
        int m = m0 + ty * 4 + i;
        int bb = m / 196, pp = m % 196;
#pragma unroll
        for (int j = 0; j < 4; j++) {
            int n = n0 + tx * 4 + j;
            float v = acc[i][j] + pb[n] + pos[(size_t)(1 + pp) * 768 + n];
            x[((size_t)bb * SMAX_ + 1 + pp) * 768 + n] = v;
        }
    }
}

__global__ void cls_pos_kernel(const float* __restrict__ cls, const float* __restrict__ pos,
                               float* __restrict__ x)
{
    int i = blockIdx.x * 256 + threadIdx.x;
    int b = i / 768, d = i % 768;
    x[(size_t)b * SMAX_ * 768 + d] = cls[d] + pos[d];
}

__global__ void build_bp_kernel(const float* __restrict__ prompts, const int* __restrict__ eid,
                                const float* __restrict__ pos, float* __restrict__ bp)
{
    int i = blockIdx.x * 256 + threadIdx.x;
    int d = i % 768;
    int r = i / 768;
    int t = r % LP_; r /= LP_;
    int pl = r % NPL_;
    int b = r / NPL_;
    int e = eid[b];
    bp[i] = prompts[(((size_t)pl * NE_ + e) * LP_ + t) * 768 + d] + pos[d];
}

__global__ void append_kernel(const float* __restrict__ bp, float* __restrict__ x, int pl)
{
    int i = blockIdx.x * 256 + threadIdx.x;
    int d = i % 768;
    int r = i / 768;
    int t = r % LP_;
    int b = r / LP_;
    x[((size_t)b * SMAX_ + S0_ + t) * 768 + d] =
        bp[(((size_t)b * NPL_ + pl) * LP_ + t) * 768 + d];
}

// ---- LayerNorm -> bf16 hi/lo splits ----
__global__ void ln_kernel(const float* __restrict__ x, const float* __restrict__ s,
                          const float* __restrict__ bb, __nv_bfloat16* __restrict__ hh,
                          __nv_bfloat16* __restrict__ hl)
{
    int row = blockIdx.x;
    int t = threadIdx.x;
    const float* xr = x + (size_t)row * 768;
    float v0 = xr[t], v1 = xr[t + 256], v2 = xr[t + 512];
    __shared__ float red[256];
    red[t] = v0 + v1 + v2;
    __syncthreads();
    for (int o = 128; o > 0; o >>= 1) { if (t < o) red[t] += red[t + o]; __syncthreads(); }
    float mean = red[0] * (1.f / 768.f);
    __syncthreads();
    float d0 = v0 - mean, d1 = v1 - mean, d2 = v2 - mean;
    red[t] = d0 * d0 + d1 * d1 + d2 * d2;
    __syncthreads();
    for (int o = 128; o > 0; o >>= 1) { if (t < o) red[t] += red[t + o]; __syncthreads(); }
    float rstd = rsqrtf(red[0] * (1.f / 768.f) + 1e-6f);
    float h0 = d0 * rstd * s[t] + bb[t];
    float h1 = d1 * rstd * s[t + 256] + bb[t + 256];
    float h2 = d2 * rstd * s[t + 512] + bb[t + 512];
    size_t ro = (size_t)row * 768;
    __nv_bfloat16 a0 = __float2bfloat16(h0), a1 = __float2bfloat16(h1), a2 = __float2bfloat16(h2);
    hh[ro + t] = a0;          hl[ro + t]       = __float2bfloat16(h0 - __bfloat162float(a0));
    hh[ro + t + 256] = a1;    hl[ro + t + 256] = __float2bfloat16(h1 - __bfloat162float(a1));
    hh[ro + t + 512] = a2;    hl[ro + t + 512] = __float2bfloat16(h2 - __bfloat162float(a2));
}

// ---- fused attention: one block per (q, head, batch); writes bf16 split o ----
__global__ void attn_kernel(const float* __restrict__ qkv, __nv_bfloat16* __restrict__ oh,
                            __nv_bfloat16* __restrict__ ol, int S)
{
    int qi = blockIdx.x, hh = blockIdx.y, b = blockIdx.z;
    int t = threadIdx.x;
    __shared__ float qs[HD_];
    __shared__ float sc[SMAX_];
    __shared__ float red[256];
    const float* base = qkv + (size_t)b * SMAX_ * 2304;

    if (t < HD_) qs[t] = base[(size_t)qi * 2304 + hh * HD_ + t];
    __syncthreads();

    if (t < S) {
        const float* kr = base + (size_t)t * 2304 + 768 + hh * HD_;
        float acc = 0.f;
#pragma unroll
        for (int d = 0; d < HD_; d++) acc += qs[d] * kr[d];
        sc[t] = acc * 0.125f;
    }
    __syncthreads();

    red[t] = (t < S) ? sc[t] : -1e30f;
    __syncthreads();
    for (int o2 = 128; o2 > 0; o2 >>= 1) { if (t < o2) red[t] = fmaxf(red[t], red[t + o2]); __syncthreads(); }
    float mx = red[0];
    __syncthreads();
    float e = (t < S) ? __expf(sc[t] - mx) : 0.f;
    red[t] = e;
    __syncthreads();
    for (int o2 = 128; o2 > 0; o2 >>= 1) { if (t < o2) red[t] += red[t + o2]; __syncthreads(); }
    float inv = 1.f / red[0];
    __syncthreads();
    if (t < S) sc[t] = e * inv;
    __syncthreads();

    if (t < HD_) {
        const float* vr = base + 1536 + hh * HD_ + t;
        float acc = 0.f;
        for (int k2 = 0; k2 < S; k2++) acc += sc[k2] * vr[(size_t)k2 * 2304];
        size_t idx = ((size_t)b * SMAX_ + qi) * 768 + hh * HD_ + t;
        __nv_bfloat16 hi = __float2bfloat16(acc);
        oh[idx] = hi;
        ol[idx] = __float2bfloat16(acc - __bfloat162float(hi));
    }
}

// ---- final LN(token 0) + expert head ----
__global__ void head_kernel(const float* __restrict__ x, const float* __restrict__ ns,
                            const float* __restrict__ nb, const int* __restrict__ eid,
                            const float* __restrict__ hw, const float* __restrict__ hb,
                            float* __restrict__ out)
{
    int b = blockIdx.x, t = threadIdx.x;
    __shared__ float feat[768];
    __shared__ float red[256];
    const float* xr = x + (size_t)b * SMAX_ * 768;
    float v0 = xr[t], v1 = xr[t + 256], v2 = xr[t + 512];
    red[t] = v0 + v1 + v2;
    __syncthreads();
    for (int o = 128; o > 0; o >>= 1) { if (t < o) red[t] += red[t + o]; __syncthreads(); }
    float mean = red[0] * (1.f / 768.f);
    __syncthreads();
    float d0 = v0 - mean, d1 = v1 - mean, d2 = v2 - mean;
    red[t] = d0 * d0 + d1 * d1 + d2 * d2;
    __syncthreads();
    for (int o = 128; o > 0; o >>= 1) { if (t < o) red[t] += red[t + o]; __syncthreads(); }
    float rstd = rsqrtf(red[0] * (1.f / 768.f) + 1e-6f);
    feat[t]       = d0 * rstd * ns[t]       + nb[t];
    feat[t + 256] = d1 * rstd * ns[t + 256] + nb[t + 256];
    feat[t + 512] = d2 * rstd * ns[t + 512] + nb[t + 512];
    __syncthreads();

    int e = eid[b];
    if (t < NC_) {
        float acc = hb[(size_t)e * NC_ + t];
        const float* w = hw + (size_t)e * 768 * NC_ + t;
        for (int d = 0; d < 768; d++) acc += feat[d] * w[(size_t)d * NC_];
        out[(size_t)b * NC_ + t] = acc;
    }
}

// ============================================================
extern "C" void kernel_launch(void* const* d_in, const int* in_sizes, int n_in,
                              void* d_out, int out_size)
{
    const float* inputs  = (const float*)d_in[0];
    const int*   eids    = (const int*)  d_in[1];
    const float* patch_w = (const float*)d_in[2];
    const float* patch_b = (const float*)d_in[3];
    const float* cls     = (const float*)d_in[4];
    const float* pos     = (const float*)d_in[5];
    const float* ln1_s   = (const float*)d_in[6];
    const float* ln1_b   = (const float*)d_in[7];
    const float* qkv_w   = (const float*)d_in[8];
    const float* qkv_b   = (const float*)d_in[9];
    const float* proj_w  = (const float*)d_in[10];
    const float* proj_b  = (const float*)d_in[11];
    const float* ln2_s   = (const float*)d_in[12];
    const float* ln2_b   = (const float*)d_in[13];
    const float* fc1_w   = (const float*)d_in[14];
    const float* fc1_b   = (const float*)d_in[15];
    const float* fc2_w   = (const float*)d_in[16];
    const float* fc2_b   = (const float*)d_in[17];
    const float* norm_s  = (const float*)d_in[18];
    const float* norm_b  = (const float*)d_in[19];
    const float* prompts = (const float*)d_in[20];
    const float* head_w  = (const float*)d_in[21];
    const float* head_b  = (const float*)d_in[22];
    float* out = (float*)d_out;

    float *x, *qkv, *bp;
    __nv_bfloat16 *hh, *hl, *oh, *ol, *mh, *ml;
    __nv_bfloat16 *wqh, *wql, *wph, *wpl, *w1h, *w1l, *w2h, *w2l;
    cudaGetSymbolAddress((void**)&x,   g_x);
    cudaGetSymbolAddress((void**)&qkv, g_qkv);
    cudaGetSymbolAddress((void**)&bp,  g_bp);
    cudaGetSymbolAddress((void**)&hh,  g_hh);
    cudaGetSymbolAddress((void**)&hl,  g_hl);
    cudaGetSymbolAddress((void**)&oh,  g_oh);
    cudaGetSymbolAddress((void**)&ol,  g_ol);
    cudaGetSymbolAddress((void**)&mh,  g_mh);
    cudaGetSymbolAddress((void**)&ml,  g_ml);
    cudaGetSymbolAddress((void**)&wqh, g_wq_h);
    cudaGetSymbolAddress((void**)&wql, g_wq_l);
    cudaGetSymbolAddress((void**)&wph, g_wp_h);
    cudaGetSymbolAddress((void**)&wpl, g_wp_l);
    cudaGetSymbolAddress((void**)&w1h, g_w1_h);
    cudaGetSymbolAddress((void**)&w1l, g_w1_l);
    cudaGetSymbolAddress((void**)&w2h, g_w2_h);
    cudaGetSymbolAddress((void**)&w2l, g_w2_l);

    // ---- weight transpose + split (once per launch) ----
    wsplit_kernel<<<dim3(3 * D_ / 32, D_ / 32, L_), dim3(32, 8)>>>(qkv_w, wqh, wql, D_, 3 * D_);
    wsplit_kernel<<<dim3(D_ / 32, D_ / 32, L_),     dim3(32, 8)>>>(proj_w, wph, wpl, D_, D_);
    wsplit_kernel<<<dim3(MLP_D / 32, D_ / 32, L_),  dim3(32, 8)>>>(fc1_w, w1h, w1l, D_, MLP_D);
    wsplit_kernel<<<dim3(D_ / 32, MLP_D / 32, L_),  dim3(32, 8)>>>(fc2_w, w2h, w2l, MLP_D, D_);

    // ---- patch embed + cls + prompts ----
    patch_embed_kernel<<<dim3(12, 98), 256>>>(inputs, patch_w, patch_b, pos, x);
    cls_pos_kernel<<<(B_ * 768) / 256, 256>>>(cls, pos, x);
    build_bp_kernel<<<(B_ * NPL_ * LP_ * 768) / 256, 256>>>(prompts, eids, pos, bp);

    const int MT = (MALL + 127) / 128;  // 60
    for (int i = 0; i < L_; i++) {
        int S = (i < NPL_) ? SMAX_ : S0_;
        if (i < NPL_)
            append_kernel<<<(B_ * LP_ * 768) / 256, 256>>>(bp, x, i);

        ln_kernel<<<MALL, 256>>>(x, ln1_s + (size_t)i * D_, ln1_b + (size_t)i * D_, hh, hl);
        mma_gemm<0, false, false><<<dim3(18, MT), 256>>>(
            hh, hl, wqh + (size_t)i * 3 * D_ * D_, wql + (size_t)i * 3 * D_ * D_,
            qkv_b + (size_t)i * 3 * D_, nullptr, qkv, nullptr, nullptr, MALL, 3 * D_, D_);
        attn_kernel<<<dim3(S, NH_, B_), 256>>>(qkv, oh, ol, S);
        mma_gemm<0, true, false><<<dim3(6, MT), 256>>>(
            oh, ol, wph + (size_t)i * D_ * D_, wpl + (size_t)i * D_ * D_,
            proj_b + (size_t)i * D_, x, x, nullptr, nullptr, MALL, D_, D_);
        ln_kernel<<<MALL, 256>>>(x, ln2_s + (size_t)i * D_, ln2_b + (size_t)i * D_, hh, hl);
        mma_gemm<1, false, true><<<dim3(24, MT), 256>>>(
            hh, hl, w1h + (size_t)i * MLP_D * D_, w1l + (size_t)i * MLP_D * D_,
            fc1_b + (size_t)i * MLP_D, nullptr, nullptr, mh, ml, MALL, MLP_D, D_);
        mma_gemm<0, true, false><<<dim3(6, MT), 256>>>(
            mh, ml, w2h + (size_t)i * D_ * MLP_D, w2l + (size_t)i * D_ * MLP_D,
            fc2_b + (size_t)i * D_, x, x, nullptr, nullptr, MALL, D_, MLP_D);
    }

    head_kernel<<<B_, 256>>>(x, norm_s, norm_b, eids, head_w, head_b, out);
}